// round 2
// baseline (speedup 1.0000x reference)
#include <cuda_runtime.h>
#include <math.h>

#define NN 100000
#define EE 1600000
#define F  128
#define G  64
#define CHUNK 512
#define NBLK ((NN + CHUNK - 1) / CHUNK)   // 196

// ---------------- device scratch (allocation-free) ----------------
__device__ float g_buf0[NN * F];   // hl = h @ W          (51.2 MB)
__device__ float g_buf1[NN * F];   // aggregated output   (51.2 MB)
__device__ float g_dinv[NN];
__device__ int   g_cnt[NN];
__device__ int   g_cur[NN];
__device__ int   g_off[NN + 1];
__device__ int   g_csrc[EE];
__device__ int   g_bsum[NBLK];
__device__ int   g_bpre[NBLK];
__device__ float g_pooled[G * F];

// ---------------- setup: degree, dinv, CSR ----------------
__global__ void k_zero() {
    int i = blockIdx.x * blockDim.x + threadIdx.x;
    if (i < NN) { g_cnt[i] = 0; g_cur[i] = 0; }
    if (i < G * F) g_pooled[i] = 0.f;
}

__global__ void k_count(const int* __restrict__ dst, int e) {
    int i = blockIdx.x * blockDim.x + threadIdx.x;
    if (i < e) atomicAdd(&g_cnt[dst[i]], 1);
}

__global__ void k_dinv(int n) {
    int i = blockIdx.x * blockDim.x + threadIdx.x;
    if (i < n) g_dinv[i] = rsqrtf((float)(g_cnt[i] + 1));   // +1 self loop
}

__global__ void k_scan1(int n) {
    __shared__ int s[CHUNK];
    int t = threadIdx.x;
    int idx = blockIdx.x * CHUNK + t;
    s[t] = (idx < n) ? g_cnt[idx] : 0;
    __syncthreads();
    for (int o = CHUNK / 2; o > 0; o >>= 1) {
        if (t < o) s[t] += s[t + o];
        __syncthreads();
    }
    if (t == 0) g_bsum[blockIdx.x] = s[0];
}

__global__ void k_scan2(int n) {
    __shared__ int s[256];
    int t = threadIdx.x;
    int v = (t < NBLK) ? g_bsum[t] : 0;
    s[t] = v;
    __syncthreads();
    for (int o = 1; o < 256; o <<= 1) {
        int x = (t >= o) ? s[t - o] : 0;
        __syncthreads();
        s[t] += x;
        __syncthreads();
    }
    if (t < NBLK) g_bpre[t] = s[t] - v;   // exclusive
    if (t == 255) g_off[n] = s[255];      // total = E
}

__global__ void k_scan3(int n) {
    __shared__ int s[CHUNK];
    int t = threadIdx.x;
    int idx = blockIdx.x * CHUNK + t;
    int v = (idx < n) ? g_cnt[idx] : 0;
    s[t] = v;
    __syncthreads();
    for (int o = 1; o < CHUNK; o <<= 1) {
        int x = (t >= o) ? s[t - o] : 0;
        __syncthreads();
        s[t] += x;
        __syncthreads();
    }
    if (idx < n) g_off[idx] = g_bpre[blockIdx.x] + s[t] - v;  // exclusive
}

__global__ void k_fill(const int* __restrict__ src, const int* __restrict__ dst, int e) {
    int i = blockIdx.x * blockDim.x + threadIdx.x;
    if (i < e) {
        int d = dst[i];
        int p = atomicAdd(&g_cur[d], 1);
        g_csrc[g_off[d] + p] = src[i];
    }
}

// ---------------- GEMM: g_buf0 = act(in) @ W ----------------
// 256 threads: col f = t&127, row group rg = t>>7 (8 rows each), 16-row tiles.
// W in smem, transposed + XOR-swizzled for conflict-free float4 column reads.
__global__ void k_gemm(const float* __restrict__ xin, const float* __restrict__ W,
                       int n, int first) {
    extern __shared__ float4 sm[];
    float4* sW = sm;            // 4096 float4 = 64 KB
    float4* sH = sm + 4096;     // 16 rows * 32 float4 = 8 KB
    const float* in = first ? xin : g_buf1;
    int t = threadIdx.x;

    // load W transposed (logical Wt[f][k]) with swizzle
    for (int i = t; i < F * F; i += 256) {
        int k = i >> 7, f = i & 127;
        float v = W[i];
        int slot = f * 32 + ((k >> 2) ^ (f & 31));
        ((float*)sW)[slot * 4 + (k & 3)] = v;
    }
    __syncthreads();

    int f = t & 127;
    int rb = (t >> 7) * 8;
    int ntiles = (n + 15) >> 4;
    for (int tile = blockIdx.x; tile < ntiles; tile += gridDim.x) {
        int row0 = tile << 4;
        for (int i = t; i < 16 * F; i += 256) {
            int r = i >> 7, k = i & 127;
            int rr = row0 + r;
            float v = (rr < n) ? in[rr * F + k] : 0.f;
            if (!first) v = fmaxf(v, 0.f);          // relu on input (layers 2,3)
            ((float*)sH)[r * F + k] = v;
        }
        __syncthreads();

        float acc[8] = {0.f, 0.f, 0.f, 0.f, 0.f, 0.f, 0.f, 0.f};
        #pragma unroll 8
        for (int k4 = 0; k4 < 32; k4++) {
            float4 wv = sW[f * 32 + (k4 ^ (f & 31))];
            #pragma unroll
            for (int r = 0; r < 8; r++) {
                float4 hv = sH[(rb + r) * 32 + k4];
                acc[r] = fmaf(hv.x, wv.x, acc[r]);
                acc[r] = fmaf(hv.y, wv.y, acc[r]);
                acc[r] = fmaf(hv.z, wv.z, acc[r]);
                acc[r] = fmaf(hv.w, wv.w, acc[r]);
            }
        }
        #pragma unroll
        for (int r = 0; r < 8; r++) {
            int rr = row0 + rb + r;
            if (rr < n) g_buf0[rr * F + f] = acc[r];
        }
        __syncthreads();
    }
}

// ---------------- Aggregation: g_buf1[d] = sum_in norm*hl[s] + self + bias ----
// Warp per dst node, lane owns one float4 (4 features). Atomic-free.
__global__ void k_agg(const float* __restrict__ bias, int n) {
    int gw = (blockIdx.x * blockDim.x + threadIdx.x) >> 5;
    int lane = threadIdx.x & 31;
    int nw = (gridDim.x * blockDim.x) >> 5;
    const float4* hl = (const float4*)g_buf0;
    float4* outp = (float4*)g_buf1;
    const float4 b = ((const float4*)bias)[lane];

    for (int nd = gw; nd < n; nd += nw) {
        float dn = g_dinv[nd];
        float sw = dn * dn;                          // self-loop norm
        float4 a = hl[nd * 32 + lane];
        float4 acc;
        acc.x = a.x * sw; acc.y = a.y * sw; acc.z = a.z * sw; acc.w = a.w * sw;
        int i = g_off[nd], iend = g_off[nd + 1];
        for (; i + 4 <= iend; i += 4) {
            int s0 = g_csrc[i], s1 = g_csrc[i + 1], s2 = g_csrc[i + 2], s3 = g_csrc[i + 3];
            float w0 = g_dinv[s0] * dn, w1 = g_dinv[s1] * dn;
            float w2 = g_dinv[s2] * dn, w3 = g_dinv[s3] * dn;
            float4 v0 = hl[s0 * 32 + lane];
            float4 v1 = hl[s1 * 32 + lane];
            float4 v2 = hl[s2 * 32 + lane];
            float4 v3 = hl[s3 * 32 + lane];
            acc.x = fmaf(v0.x, w0, fmaf(v1.x, w1, fmaf(v2.x, w2, fmaf(v3.x, w3, acc.x))));
            acc.y = fmaf(v0.y, w0, fmaf(v1.y, w1, fmaf(v2.y, w2, fmaf(v3.y, w3, acc.y))));
            acc.z = fmaf(v0.z, w0, fmaf(v1.z, w1, fmaf(v2.z, w2, fmaf(v3.z, w3, acc.z))));
            acc.w = fmaf(v0.w, w0, fmaf(v1.w, w1, fmaf(v2.w, w2, fmaf(v3.w, w3, acc.w))));
        }
        for (; i < iend; i++) {
            int s = g_csrc[i];
            float w = g_dinv[s] * dn;
            float4 v = hl[s * 32 + lane];
            acc.x = fmaf(v.x, w, acc.x);
            acc.y = fmaf(v.y, w, acc.y);
            acc.z = fmaf(v.z, w, acc.z);
            acc.w = fmaf(v.w, w, acc.w);
        }
        acc.x += b.x; acc.y += b.y; acc.z += b.z; acc.w += b.w;
        outp[nd * 32 + lane] = acc;
    }
}

// ---------------- Pooling: segment_max(relu(h), batch) ----------------
// batch is sorted: keep running max in a register, flush on graph change.
// relu(h) >= 0, so int-bitwise atomicMax is order-correct and 0-init works.
__global__ void k_pool(const int* __restrict__ batch, int n) {
    int f = threadIdx.x;
    int n0 = blockIdx.x * CHUNK;
    if (n0 >= n) return;
    int n1 = min(n0 + CHUNK, n);
    int cur = batch[n0];
    float m = 0.f;                                   // relu floor
    for (int nd = n0; nd < n1; nd++) {
        int gg = batch[nd];
        if (gg != cur) {
            atomicMax((int*)&g_pooled[cur * F + f], __float_as_int(m));
            cur = gg;
            m = 0.f;
        }
        m = fmaxf(m, g_buf1[nd * F + f]);            // max(relu floor, h) == max over relu(h)
    }
    atomicMax((int*)&g_pooled[cur * F + f], __float_as_int(m));
}

// ---------------- Head: (pooled@Wp1+bp1)@Wp2+bp2, log_softmax ----------------
__global__ void k_head(const float* __restrict__ Wp1, const float* __restrict__ bp1,
                       const float* __restrict__ Wp2, const float* __restrict__ bp2,
                       float* __restrict__ out) {
    __shared__ float sp[F];
    __shared__ float t1[F];
    int t = threadIdx.x, g = blockIdx.x;
    sp[t] = g_pooled[g * F + t];
    __syncthreads();
    float a = bp1[t];
    #pragma unroll 4
    for (int k = 0; k < F; k++) a = fmaf(sp[k], Wp1[k * F + t], a);
    t1[t] = a;
    __syncthreads();
    if (t == 0) {
        float l0 = bp2[0], l1 = bp2[1];
        for (int k = 0; k < F; k++) {
            l0 = fmaf(t1[k], Wp2[2 * k], l0);
            l1 = fmaf(t1[k], Wp2[2 * k + 1], l1);
        }
        float m = fmaxf(l0, l1);
        float lse = m + logf(expf(l0 - m) + expf(l1 - m));
        out[2 * g] = l0 - lse;
        out[2 * g + 1] = l1 - lse;
    }
}

// ---------------- launch ----------------
extern "C" void kernel_launch(void* const* d_in, const int* in_sizes, int n_in,
                              void* d_out, int out_size) {
    const float* x   = (const float*)d_in[0];
    const int*   ei  = (const int*)d_in[1];
    const int*   bat = (const int*)d_in[2];
    const float* W1  = (const float*)d_in[3];  const float* b1  = (const float*)d_in[4];
    const float* W2  = (const float*)d_in[5];  const float* b2  = (const float*)d_in[6];
    const float* W3  = (const float*)d_in[7];  const float* b3  = (const float*)d_in[8];
    const float* Wp1 = (const float*)d_in[9];  const float* bp1 = (const float*)d_in[10];
    const float* Wp2 = (const float*)d_in[11]; const float* bp2 = (const float*)d_in[12];
    float* out = (float*)d_out;

    int n = in_sizes[0] / F;        // 100000
    int e = in_sizes[1] / 2;        // 1600000
    const int* src = ei;
    const int* dst = ei + e;

    cudaFuncSetAttribute(k_gemm, cudaFuncAttributeMaxDynamicSharedMemorySize, 73728);
    size_t smem = 73728;

    k_zero<<<(NN + 255) / 256, 256>>>();
    k_count<<<(e + 255) / 256, 256>>>(dst, e);
    k_dinv<<<(n + 255) / 256, 256>>>(n);
    k_scan1<<<NBLK, CHUNK>>>(n);
    k_scan2<<<1, 256>>>(n);
    k_scan3<<<NBLK, CHUNK>>>(n);
    k_fill<<<(e + 255) / 256, 256>>>(src, dst, e);

    k_gemm<<<444, 256, smem>>>(x, W1, n, 1);
    k_agg<<<1184, 256>>>(b1, n);
    k_gemm<<<444, 256, smem>>>(x, W2, n, 0);
    k_agg<<<1184, 256>>>(b2, n);
    k_gemm<<<444, 256, smem>>>(x, W3, n, 0);
    k_agg<<<1184, 256>>>(b3, n);

    k_pool<<<NBLK, F>>>(bat, n);
    k_head<<<G, F>>>(Wp1, bp1, Wp2, bp2, out);
}

// round 3
// speedup vs baseline: 1.2902x; 1.2902x over previous
#include <cuda_runtime.h>
#include <mma.h>
#include <math.h>

using namespace nvcuda;

#define NN 100000
#define NPAD (NN + 64)
#define EE 1600000
#define F  128
#define G  64
#define CHUNK 512
#define NBLK ((NN + CHUNK - 1) / CHUNK)   // 196
#define ASTR 132
#define WSTR 132

// ---------------- device scratch (allocation-free) ----------------
__device__ float g_buf0[NPAD * F];   // hl = h @ W   (padded for unguarded wmma stores)
__device__ float g_buf1[NPAD * F];   // aggregated output
__device__ float g_dinv[NN];
__device__ int   g_cnt[NN];
__device__ int   g_cur[NN];
__device__ int   g_off[NN + 1];
__device__ int   g_csrc[EE];
__device__ int   g_bsum[NBLK];
__device__ int   g_bpre[NBLK];
__device__ float g_pooled[G * F];

// ---------------- setup: degree, dinv, CSR ----------------
__global__ void k_zero() {
    int i = blockIdx.x * blockDim.x + threadIdx.x;
    if (i < NN) { g_cnt[i] = 0; g_cur[i] = 0; }
    if (i < G * F) g_pooled[i] = 0.f;
}

__global__ void k_count(const int* __restrict__ dst, int e) {
    int i = blockIdx.x * blockDim.x + threadIdx.x;
    if (i < e) atomicAdd(&g_cnt[dst[i]], 1);
}

__global__ void k_dinv(int n) {
    int i = blockIdx.x * blockDim.x + threadIdx.x;
    if (i < n) g_dinv[i] = rsqrtf((float)(g_cnt[i] + 1));   // +1 self loop
}

__global__ void k_scan1(int n) {
    __shared__ int s[CHUNK];
    int t = threadIdx.x;
    int idx = blockIdx.x * CHUNK + t;
    s[t] = (idx < n) ? g_cnt[idx] : 0;
    __syncthreads();
    for (int o = CHUNK / 2; o > 0; o >>= 1) {
        if (t < o) s[t] += s[t + o];
        __syncthreads();
    }
    if (t == 0) g_bsum[blockIdx.x] = s[0];
}

__global__ void k_scan2(int n) {
    __shared__ int s[256];
    int t = threadIdx.x;
    int v = (t < NBLK) ? g_bsum[t] : 0;
    s[t] = v;
    __syncthreads();
    for (int o = 1; o < 256; o <<= 1) {
        int x = (t >= o) ? s[t - o] : 0;
        __syncthreads();
        s[t] += x;
        __syncthreads();
    }
    if (t < NBLK) g_bpre[t] = s[t] - v;   // exclusive
    if (t == 255) g_off[n] = s[255];      // total = E
}

__global__ void k_scan3(int n) {
    __shared__ int s[CHUNK];
    int t = threadIdx.x;
    int idx = blockIdx.x * CHUNK + t;
    int v = (idx < n) ? g_cnt[idx] : 0;
    s[t] = v;
    __syncthreads();
    for (int o = 1; o < CHUNK; o <<= 1) {
        int x = (t >= o) ? s[t - o] : 0;
        __syncthreads();
        s[t] += x;
        __syncthreads();
    }
    if (idx < n) g_off[idx] = g_bpre[blockIdx.x] + s[t] - v;  // exclusive
}

__global__ void k_fill(const int* __restrict__ src, const int* __restrict__ dst, int e) {
    int i = blockIdx.x * blockDim.x + threadIdx.x;
    if (i < e) {
        int d = dst[i];
        int p = atomicAdd(&g_cur[d], 1);
        g_csrc[g_off[d] + p] = src[i];
    }
}

// ---------------- GEMM (tf32 tensor cores): g_buf0 = act(in) @ W ----------------
// Persistent blocks, 256 threads = 8 warps. Tile = 64 rows x 128 cols.
// Warp (r,c) grid 2x4: each warp computes 32x32 via 2x2 wmma m16n16k8 frags.
// W staged once per block in smem (tf32), A tile staged per iteration (relu fused).
__global__ void k_gemm_tc(const float* __restrict__ xin, const float* __restrict__ W,
                          int n, int first) {
    extern __shared__ float sm[];
    float* sW = sm;                 // 128 x WSTR
    float* sA = sm + 128 * WSTR;    // 64 x ASTR
    int t = threadIdx.x;
    const float* in = first ? xin : g_buf1;

    // stage W (row-major [k][f]) as tf32
    for (int i = t; i < F * F; i += 256) {
        int k = i >> 7, f = i & 127;
        sW[k * WSTR + f] = wmma::__float_to_tf32(W[i]);
    }

    int warp = t >> 5;
    int wr = (warp & 1) * 32;       // row offset within tile
    int wc = (warp >> 1) * 32;      // col offset

    int ntiles = (n + 63) >> 6;
    for (int tile = blockIdx.x; tile < ntiles; tile += gridDim.x) {
        int row0 = tile << 6;
        __syncthreads();            // protect sA reuse (and first-pass sW)
        // stage A tile 64x128, relu on layers 2/3, convert to tf32
        for (int i = t * 4; i < 64 * F; i += 256 * 4) {
            int r = i >> 7, k = i & 127;
            int rr = row0 + r;
            float4 v = make_float4(0.f, 0.f, 0.f, 0.f);
            if (rr < n) v = *(const float4*)&in[rr * F + k];
            if (!first) {
                v.x = fmaxf(v.x, 0.f); v.y = fmaxf(v.y, 0.f);
                v.z = fmaxf(v.z, 0.f); v.w = fmaxf(v.w, 0.f);
            }
            float* d = &sA[r * ASTR + k];
            d[0] = wmma::__float_to_tf32(v.x);
            d[1] = wmma::__float_to_tf32(v.y);
            d[2] = wmma::__float_to_tf32(v.z);
            d[3] = wmma::__float_to_tf32(v.w);
        }
        __syncthreads();

        wmma::fragment<wmma::accumulator, 16, 16, 8, float> c[2][2];
        #pragma unroll
        for (int i = 0; i < 2; i++)
            #pragma unroll
            for (int j = 0; j < 2; j++)
                wmma::fill_fragment(c[i][j], 0.f);

        #pragma unroll
        for (int k0 = 0; k0 < F; k0 += 8) {
            wmma::fragment<wmma::matrix_a, 16, 16, 8, wmma::precision::tf32, wmma::row_major> a0, a1;
            wmma::fragment<wmma::matrix_b, 16, 16, 8, wmma::precision::tf32, wmma::row_major> b0, b1;
            wmma::load_matrix_sync(a0, &sA[wr * ASTR + k0], ASTR);
            wmma::load_matrix_sync(a1, &sA[(wr + 16) * ASTR + k0], ASTR);
            wmma::load_matrix_sync(b0, &sW[k0 * WSTR + wc], WSTR);
            wmma::load_matrix_sync(b1, &sW[k0 * WSTR + wc + 16], WSTR);
            wmma::mma_sync(c[0][0], a0, b0, c[0][0]);
            wmma::mma_sync(c[0][1], a0, b1, c[0][1]);
            wmma::mma_sync(c[1][0], a1, b0, c[1][0]);
            wmma::mma_sync(c[1][1], a1, b1, c[1][1]);
        }

        // unguarded stores: g_buf0 is padded to NPAD rows
        #pragma unroll
        for (int i = 0; i < 2; i++)
            #pragma unroll
            for (int j = 0; j < 2; j++)
                wmma::store_matrix_sync(&g_buf0[(row0 + wr + 16 * i) * F + wc + 16 * j],
                                        c[i][j], F, wmma::mem_row_major);
    }
}

// ---------------- Aggregation: g_buf1[d] = sum_in norm*hl[s] + self + bias ----
__global__ void k_agg(const float* __restrict__ bias, int n) {
    int gw = (blockIdx.x * blockDim.x + threadIdx.x) >> 5;
    int lane = threadIdx.x & 31;
    int nw = (gridDim.x * blockDim.x) >> 5;
    const float4* hl = (const float4*)g_buf0;
    float4* outp = (float4*)g_buf1;
    const float4 b = ((const float4*)bias)[lane];

    for (int nd = gw; nd < n; nd += nw) {
        float dn = g_dinv[nd];
        float sw = dn * dn;                          // self-loop norm
        float4 a = hl[nd * 32 + lane];
        float4 acc;
        acc.x = a.x * sw; acc.y = a.y * sw; acc.z = a.z * sw; acc.w = a.w * sw;
        int i = g_off[nd], iend = g_off[nd + 1];
        for (; i + 4 <= iend; i += 4) {
            int s0 = g_csrc[i], s1 = g_csrc[i + 1], s2 = g_csrc[i + 2], s3 = g_csrc[i + 3];
            float w0 = g_dinv[s0] * dn, w1 = g_dinv[s1] * dn;
            float w2 = g_dinv[s2] * dn, w3 = g_dinv[s3] * dn;
            float4 v0 = hl[s0 * 32 + lane];
            float4 v1 = hl[s1 * 32 + lane];
            float4 v2 = hl[s2 * 32 + lane];
            float4 v3 = hl[s3 * 32 + lane];
            acc.x = fmaf(v0.x, w0, fmaf(v1.x, w1, fmaf(v2.x, w2, fmaf(v3.x, w3, acc.x))));
            acc.y = fmaf(v0.y, w0, fmaf(v1.y, w1, fmaf(v2.y, w2, fmaf(v3.y, w3, acc.y))));
            acc.z = fmaf(v0.z, w0, fmaf(v1.z, w1, fmaf(v2.z, w2, fmaf(v3.z, w3, acc.z))));
            acc.w = fmaf(v0.w, w0, fmaf(v1.w, w1, fmaf(v2.w, w2, fmaf(v3.w, w3, acc.w))));
        }
        for (; i < iend; i++) {
            int s = g_csrc[i];
            float w = g_dinv[s] * dn;
            float4 v = hl[s * 32 + lane];
            acc.x = fmaf(v.x, w, acc.x);
            acc.y = fmaf(v.y, w, acc.y);
            acc.z = fmaf(v.z, w, acc.z);
            acc.w = fmaf(v.w, w, acc.w);
        }
        acc.x += b.x; acc.y += b.y; acc.z += b.z; acc.w += b.w;
        outp[nd * 32 + lane] = acc;
    }
}

// ---------------- Pooling: segment_max(relu(h), batch) ----------------
__global__ void k_pool(const int* __restrict__ batch, int n) {
    int f = threadIdx.x;
    int n0 = blockIdx.x * CHUNK;
    if (n0 >= n) return;
    int n1 = min(n0 + CHUNK, n);
    int cur = batch[n0];
    float m = 0.f;                                   // relu floor
    for (int nd = n0; nd < n1; nd++) {
        int gg = batch[nd];
        if (gg != cur) {
            atomicMax((int*)&g_pooled[cur * F + f], __float_as_int(m));
            cur = gg;
            m = 0.f;
        }
        m = fmaxf(m, g_buf1[nd * F + f]);
    }
    atomicMax((int*)&g_pooled[cur * F + f], __float_as_int(m));
}

// ---------------- Head ----------------
__global__ void k_head(const float* __restrict__ Wp1, const float* __restrict__ bp1,
                       const float* __restrict__ Wp2, const float* __restrict__ bp2,
                       float* __restrict__ out) {
    __shared__ float sp[F];
    __shared__ float t1[F];
    int t = threadIdx.x, g = blockIdx.x;
    sp[t] = g_pooled[g * F + t];
    __syncthreads();
    float a = bp1[t];
    #pragma unroll 4
    for (int k = 0; k < F; k++) a = fmaf(sp[k], Wp1[k * F + t], a);
    t1[t] = a;
    __syncthreads();
    if (t == 0) {
        float l0 = bp2[0], l1 = bp2[1];
        for (int k = 0; k < F; k++) {
            l0 = fmaf(t1[k], Wp2[2 * k], l0);
            l1 = fmaf(t1[k], Wp2[2 * k + 1], l1);
        }
        float m = fmaxf(l0, l1);
        float lse = m + logf(expf(l0 - m) + expf(l1 - m));
        out[2 * g] = l0 - lse;
        out[2 * g + 1] = l1 - lse;
    }
}

// ---------------- launch ----------------
extern "C" void kernel_launch(void* const* d_in, const int* in_sizes, int n_in,
                              void* d_out, int out_size) {
    const float* x   = (const float*)d_in[0];
    const int*   ei  = (const int*)d_in[1];
    const int*   bat = (const int*)d_in[2];
    const float* W1  = (const float*)d_in[3];  const float* b1  = (const float*)d_in[4];
    const float* W2  = (const float*)d_in[5];  const float* b2  = (const float*)d_in[6];
    const float* W3  = (const float*)d_in[7];  const float* b3  = (const float*)d_in[8];
    const float* Wp1 = (const float*)d_in[9];  const float* bp1 = (const float*)d_in[10];
    const float* Wp2 = (const float*)d_in[11]; const float* bp2 = (const float*)d_in[12];
    float* out = (float*)d_out;

    int n = in_sizes[0] / F;        // 100000
    int e = in_sizes[1] / 2;        // 1600000
    const int* src = ei;
    const int* dst = ei + e;

    size_t smem = (size_t)(128 * WSTR + 64 * ASTR) * sizeof(float);   // 101376 B
    cudaFuncSetAttribute(k_gemm_tc, cudaFuncAttributeMaxDynamicSharedMemorySize, (int)smem);

    k_zero<<<(NN + 255) / 256, 256>>>();
    k_count<<<(e + 255) / 256, 256>>>(dst, e);
    k_dinv<<<(n + 255) / 256, 256>>>(n);
    k_scan1<<<NBLK, CHUNK>>>(n);
    k_scan2<<<1, 256>>>(n);
    k_scan3<<<NBLK, CHUNK>>>(n);
    k_fill<<<(e + 255) / 256, 256>>>(src, dst, e);

    k_gemm_tc<<<296, 256, smem>>>(x, W1, n, 1);
    k_agg<<<1184, 256>>>(b1, n);
    k_gemm_tc<<<296, 256, smem>>>(x, W2, n, 0);
    k_agg<<<1184, 256>>>(b2, n);
    k_gemm_tc<<<296, 256, smem>>>(x, W3, n, 0);
    k_agg<<<1184, 256>>>(b3, n);

    k_pool<<<NBLK, F>>>(bat, n);
    k_head<<<G, F>>>(Wp1, bp1, Wp2, bp2, out);
}

// round 4
// speedup vs baseline: 1.3061x; 1.0124x over previous
#include <cuda_runtime.h>
#include <cuda_fp16.h>
#include <mma.h>
#include <math.h>

using namespace nvcuda;

#define NN 100000
#define NPAD (NN + 64)
#define EE 1600000
#define F  128
#define G  64
#define CHUNK 512
#define NBLK ((NN + CHUNK - 1) / CHUNK)   // 196
#define ASTR 132
#define WSTR 132

// ---------------- device scratch (allocation-free) ----------------
__device__ __half g_half[NPAD * F];  // hl = h @ W, fp16 (25.6 MB)
__device__ float  g_buf1[NPAD * F];  // aggregated output, fp32 (51.2 MB)
__device__ float  g_dinv[NN];
__device__ int    g_cnt[NN];
__device__ int    g_cur[NN];
__device__ int    g_off[NN + 1];
__device__ int    g_csrc[EE];
__device__ int    g_bsum[NBLK];
__device__ int    g_bpre[NBLK];
__device__ float  g_pooled[G * F];

__device__ __forceinline__ float4 ld_h4(const __half* p) {
    uint2 u = *(const uint2*)p;
    float2 a = __half22float2(*reinterpret_cast<__half2*>(&u.x));
    float2 b = __half22float2(*reinterpret_cast<__half2*>(&u.y));
    return make_float4(a.x, a.y, b.x, b.y);
}

// ---------------- setup: degree, dinv, CSR ----------------
__global__ void k_zero() {
    int i = blockIdx.x * blockDim.x + threadIdx.x;
    if (i < NN) { g_cnt[i] = 0; g_cur[i] = 0; }
    if (i < G * F) g_pooled[i] = 0.f;
}

__global__ void k_count(const int* __restrict__ dst, int e) {
    int i = blockIdx.x * blockDim.x + threadIdx.x;
    if (i < e) atomicAdd(&g_cnt[dst[i]], 1);
}

__global__ void k_dinv(int n) {
    int i = blockIdx.x * blockDim.x + threadIdx.x;
    if (i < n) g_dinv[i] = rsqrtf((float)(g_cnt[i] + 1));   // +1 self loop
}

__global__ void k_scan1(int n) {
    __shared__ int s[CHUNK];
    int t = threadIdx.x;
    int idx = blockIdx.x * CHUNK + t;
    s[t] = (idx < n) ? g_cnt[idx] : 0;
    __syncthreads();
    for (int o = CHUNK / 2; o > 0; o >>= 1) {
        if (t < o) s[t] += s[t + o];
        __syncthreads();
    }
    if (t == 0) g_bsum[blockIdx.x] = s[0];
}

__global__ void k_scan2(int n) {
    __shared__ int s[256];
    int t = threadIdx.x;
    int v = (t < NBLK) ? g_bsum[t] : 0;
    s[t] = v;
    __syncthreads();
    for (int o = 1; o < 256; o <<= 1) {
        int x = (t >= o) ? s[t - o] : 0;
        __syncthreads();
        s[t] += x;
        __syncthreads();
    }
    if (t < NBLK) g_bpre[t] = s[t] - v;   // exclusive
    if (t == 255) g_off[n] = s[255];      // total = E
}

__global__ void k_scan3(int n) {
    __shared__ int s[CHUNK];
    int t = threadIdx.x;
    int idx = blockIdx.x * CHUNK + t;
    int v = (idx < n) ? g_cnt[idx] : 0;
    s[t] = v;
    __syncthreads();
    for (int o = 1; o < CHUNK; o <<= 1) {
        int x = (t >= o) ? s[t - o] : 0;
        __syncthreads();
        s[t] += x;
        __syncthreads();
    }
    if (idx < n) g_off[idx] = g_bpre[blockIdx.x] + s[t] - v;  // exclusive
}

__global__ void k_fill(const int* __restrict__ src, const int* __restrict__ dst, int e) {
    int i = blockIdx.x * blockDim.x + threadIdx.x;
    if (i < e) {
        int d = dst[i];
        int p = atomicAdd(&g_cur[d], 1);
        g_csrc[g_off[d] + p] = src[i];
    }
}

// ---------------- GEMM (tf32 tensor cores): g_half = act(in) @ W ----------------
// Persistent blocks, 256 threads = 8 warps. Tile = 64 rows x 128 cols.
// Epilogue: frags -> smem (reuse sA) -> fp16 global.
__global__ void k_gemm_tc(const float* __restrict__ xin, const float* __restrict__ W,
                          int n, int first) {
    extern __shared__ float sm[];
    float* sW = sm;                 // 128 x WSTR
    float* sA = sm + 128 * WSTR;    // 64 x ASTR (doubles as C tile in epilogue)
    int t = threadIdx.x;
    const float* in = first ? xin : g_buf1;

    for (int i = t; i < F * F; i += 256) {
        int k = i >> 7, f = i & 127;
        sW[k * WSTR + f] = wmma::__float_to_tf32(W[i]);
    }

    int warp = t >> 5;
    int wr = (warp & 1) * 32;
    int wc = (warp >> 1) * 32;

    int ntiles = (n + 63) >> 6;
    for (int tile = blockIdx.x; tile < ntiles; tile += gridDim.x) {
        int row0 = tile << 6;
        __syncthreads();            // protect sA reuse (and first-pass sW)
        for (int i = t * 4; i < 64 * F; i += 256 * 4) {
            int r = i >> 7, k = i & 127;
            int rr = row0 + r;
            float4 v = make_float4(0.f, 0.f, 0.f, 0.f);
            if (rr < n) v = *(const float4*)&in[rr * F + k];
            if (!first) {
                v.x = fmaxf(v.x, 0.f); v.y = fmaxf(v.y, 0.f);
                v.z = fmaxf(v.z, 0.f); v.w = fmaxf(v.w, 0.f);
            }
            float* d = &sA[r * ASTR + k];
            d[0] = wmma::__float_to_tf32(v.x);
            d[1] = wmma::__float_to_tf32(v.y);
            d[2] = wmma::__float_to_tf32(v.z);
            d[3] = wmma::__float_to_tf32(v.w);
        }
        __syncthreads();

        wmma::fragment<wmma::accumulator, 16, 16, 8, float> c[2][2];
        #pragma unroll
        for (int i = 0; i < 2; i++)
            #pragma unroll
            for (int j = 0; j < 2; j++)
                wmma::fill_fragment(c[i][j], 0.f);

        #pragma unroll
        for (int k0 = 0; k0 < F; k0 += 8) {
            wmma::fragment<wmma::matrix_a, 16, 16, 8, wmma::precision::tf32, wmma::row_major> a0, a1;
            wmma::fragment<wmma::matrix_b, 16, 16, 8, wmma::precision::tf32, wmma::row_major> b0, b1;
            wmma::load_matrix_sync(a0, &sA[wr * ASTR + k0], ASTR);
            wmma::load_matrix_sync(a1, &sA[(wr + 16) * ASTR + k0], ASTR);
            wmma::load_matrix_sync(b0, &sW[k0 * WSTR + wc], WSTR);
            wmma::load_matrix_sync(b1, &sW[k0 * WSTR + wc + 16], WSTR);
            wmma::mma_sync(c[0][0], a0, b0, c[0][0]);
            wmma::mma_sync(c[0][1], a0, b1, c[0][1]);
            wmma::mma_sync(c[1][0], a1, b0, c[1][0]);
            wmma::mma_sync(c[1][1], a1, b1, c[1][1]);
        }

        __syncthreads();            // all warps done reading sA
        #pragma unroll
        for (int i = 0; i < 2; i++)
            #pragma unroll
            for (int j = 0; j < 2; j++)
                wmma::store_matrix_sync(&sA[(wr + 16 * i) * ASTR + wc + 16 * j],
                                        c[i][j], ASTR, wmma::mem_row_major);
        __syncthreads();

        // convert C tile to fp16, write to g_half (padded, unguarded)
        for (int i = t * 4; i < 64 * F; i += 256 * 4) {
            int r = i >> 7, k = i & 127;
            float4 v = *(const float4*)&sA[r * ASTR + k];
            __half2 h0 = __floats2half2_rn(v.x, v.y);
            __half2 h1 = __floats2half2_rn(v.z, v.w);
            uint2 u;
            u.x = *reinterpret_cast<unsigned*>(&h0);
            u.y = *reinterpret_cast<unsigned*>(&h1);
            *(uint2*)&g_half[(row0 + r) * F + k] = u;
        }
    }
}

// ---------------- Aggregation: g_buf1[d] = sum_in norm*hl[s] + self + bias ----
// Warp per dst node, lane owns 4 features (one uint2 of fp16). Atomic-free.
__global__ void k_agg(const float* __restrict__ bias, int n) {
    int gw = (blockIdx.x * blockDim.x + threadIdx.x) >> 5;
    int lane = threadIdx.x & 31;
    int nw = (gridDim.x * blockDim.x) >> 5;
    const __half* hl = g_half;
    float4* outp = (float4*)g_buf1;
    const float4 b = ((const float4*)bias)[lane];
    int fo = lane * 4;

    for (int nd = gw; nd < n; nd += nw) {
        float dn = g_dinv[nd];
        float sw = dn * dn;
        float4 a = ld_h4(hl + nd * F + fo);
        float4 acc;
        acc.x = a.x * sw; acc.y = a.y * sw; acc.z = a.z * sw; acc.w = a.w * sw;
        int i = g_off[nd], iend = g_off[nd + 1];
        for (; i + 4 <= iend; i += 4) {
            int s0 = g_csrc[i], s1 = g_csrc[i + 1], s2 = g_csrc[i + 2], s3 = g_csrc[i + 3];
            float w0 = g_dinv[s0] * dn, w1 = g_dinv[s1] * dn;
            float w2 = g_dinv[s2] * dn, w3 = g_dinv[s3] * dn;
            float4 v0 = ld_h4(hl + s0 * F + fo);
            float4 v1 = ld_h4(hl + s1 * F + fo);
            float4 v2 = ld_h4(hl + s2 * F + fo);
            float4 v3 = ld_h4(hl + s3 * F + fo);
            acc.x = fmaf(v0.x, w0, fmaf(v1.x, w1, fmaf(v2.x, w2, fmaf(v3.x, w3, acc.x))));
            acc.y = fmaf(v0.y, w0, fmaf(v1.y, w1, fmaf(v2.y, w2, fmaf(v3.y, w3, acc.y))));
            acc.z = fmaf(v0.z, w0, fmaf(v1.z, w1, fmaf(v2.z, w2, fmaf(v3.z, w3, acc.z))));
            acc.w = fmaf(v0.w, w0, fmaf(v1.w, w1, fmaf(v2.w, w2, fmaf(v3.w, w3, acc.w))));
        }
        for (; i < iend; i++) {
            int s = g_csrc[i];
            float w = g_dinv[s] * dn;
            float4 v = ld_h4(hl + s * F + fo);
            acc.x = fmaf(v.x, w, acc.x);
            acc.y = fmaf(v.y, w, acc.y);
            acc.z = fmaf(v.z, w, acc.z);
            acc.w = fmaf(v.w, w, acc.w);
        }
        acc.x += b.x; acc.y += b.y; acc.z += b.z; acc.w += b.w;
        outp[nd * 32 + lane] = acc;
    }
}

// ---------------- Pooling: segment_max(relu(h), batch) ----------------
__global__ void k_pool(const int* __restrict__ batch, int n) {
    int f = threadIdx.x;
    int n0 = blockIdx.x * CHUNK;
    if (n0 >= n) return;
    int n1 = min(n0 + CHUNK, n);
    int cur = batch[n0];
    float m = 0.f;
    for (int nd = n0; nd < n1; nd++) {
        int gg = batch[nd];
        if (gg != cur) {
            atomicMax((int*)&g_pooled[cur * F + f], __float_as_int(m));
            cur = gg;
            m = 0.f;
        }
        m = fmaxf(m, g_buf1[nd * F + f]);
    }
    atomicMax((int*)&g_pooled[cur * F + f], __float_as_int(m));
}

// ---------------- Head ----------------
__global__ void k_head(const float* __restrict__ Wp1, const float* __restrict__ bp1,
                       const float* __restrict__ Wp2, const float* __restrict__ bp2,
                       float* __restrict__ out) {
    __shared__ float sp[F];
    __shared__ float t1[F];
    int t = threadIdx.x, g = blockIdx.x;
    sp[t] = g_pooled[g * F + t];
    __syncthreads();
    float a = bp1[t];
    #pragma unroll 4
    for (int k = 0; k < F; k++) a = fmaf(sp[k], Wp1[k * F + t], a);
    t1[t] = a;
    __syncthreads();
    if (t == 0) {
        float l0 = bp2[0], l1 = bp2[1];
        for (int k = 0; k < F; k++) {
            l0 = fmaf(t1[k], Wp2[2 * k], l0);
            l1 = fmaf(t1[k], Wp2[2 * k + 1], l1);
        }
        float m = fmaxf(l0, l1);
        float lse = m + logf(expf(l0 - m) + expf(l1 - m));
        out[2 * g] = l0 - lse;
        out[2 * g + 1] = l1 - lse;
    }
}

// ---------------- launch ----------------
extern "C" void kernel_launch(void* const* d_in, const int* in_sizes, int n_in,
                              void* d_out, int out_size) {
    const float* x   = (const float*)d_in[0];
    const int*   ei  = (const int*)d_in[1];
    const int*   bat = (const int*)d_in[2];
    const float* W1  = (const float*)d_in[3];  const float* b1  = (const float*)d_in[4];
    const float* W2  = (const float*)d_in[5];  const float* b2  = (const float*)d_in[6];
    const float* W3  = (const float*)d_in[7];  const float* b3  = (const float*)d_in[8];
    const float* Wp1 = (const float*)d_in[9];  const float* bp1 = (const float*)d_in[10];
    const float* Wp2 = (const float*)d_in[11]; const float* bp2 = (const float*)d_in[12];
    float* out = (float*)d_out;

    int n = in_sizes[0] / F;        // 100000
    int e = in_sizes[1] / 2;        // 1600000
    const int* src = ei;
    const int* dst = ei + e;

    size_t smem = (size_t)(128 * WSTR + 64 * ASTR) * sizeof(float);   // 101376 B
    cudaFuncSetAttribute(k_gemm_tc, cudaFuncAttributeMaxDynamicSharedMemorySize, (int)smem);

    k_zero<<<(NN + 255) / 256, 256>>>();
    k_count<<<(e + 255) / 256, 256>>>(dst, e);
    k_dinv<<<(n + 255) / 256, 256>>>(n);
    k_scan1<<<NBLK, CHUNK>>>(n);
    k_scan2<<<1, 256>>>(n);
    k_scan3<<<NBLK, CHUNK>>>(n);
    k_fill<<<(e + 255) / 256, 256>>>(src, dst, e);

    k_gemm_tc<<<296, 256, smem>>>(x, W1, n, 1);
    k_agg<<<1184, 256>>>(b1, n);
    k_gemm_tc<<<296, 256, smem>>>(x, W2, n, 0);
    k_agg<<<1184, 256>>>(b2, n);
    k_gemm_tc<<<296, 256, smem>>>(x, W3, n, 0);
    k_agg<<<1184, 256>>>(b3, n);

    k_pool<<<NBLK, F>>>(bat, n);
    k_head<<<G, F>>>(Wp1, bp1, Wp2, bp2, out);
}

// round 5
// speedup vs baseline: 1.4010x; 1.0726x over previous
#include <cuda_runtime.h>
#include <cuda_fp16.h>
#include <mma.h>
#include <math.h>

using namespace nvcuda;

#define NN 100000
#define NPAD (NN + 64)
#define EE 1600000
#define F  128
#define G  64
#define CHUNK 512
#define NBLK ((NN + CHUNK - 1) / CHUNK)   // 196
#define ASTR 132
#define WSTR 132

// ---------------- device scratch (allocation-free) ----------------
__device__ __half g_half[NPAD * F];  // hl = h @ W, fp16          (25.6 MB)
__device__ __half g_hin[NPAD * F];   // relu(agg) output, fp16    (25.6 MB)
__device__ float  g_dinv[NN];
__device__ int    g_cnt[NN];
__device__ int    g_cur[NN];
__device__ int    g_off[NN + 1];
__device__ int2   g_ew[EE];          // {src, norm weight bits}   (12.8 MB)
__device__ int    g_bsum[NBLK];
__device__ int    g_bpre[NBLK];
__device__ float  g_pooled[G * F];

// ---------------- setup: degree, dinv, CSR ----------------
__global__ void k_zero() {
    int i = blockIdx.x * blockDim.x + threadIdx.x;
    if (i < NN) { g_cnt[i] = 0; g_cur[i] = 0; }
    if (i < G * F) g_pooled[i] = 0.f;
}

__global__ void k_count(const int* __restrict__ dst, int e) {
    int i = blockIdx.x * blockDim.x + threadIdx.x;
    if (i < e) atomicAdd(&g_cnt[dst[i]], 1);
}

__global__ void k_dinv(int n) {
    int i = blockIdx.x * blockDim.x + threadIdx.x;
    if (i < n) g_dinv[i] = rsqrtf((float)(g_cnt[i] + 1));   // +1 self loop
}

__global__ void k_scan1(int n) {
    __shared__ int s[CHUNK];
    int t = threadIdx.x;
    int idx = blockIdx.x * CHUNK + t;
    s[t] = (idx < n) ? g_cnt[idx] : 0;
    __syncthreads();
    for (int o = CHUNK / 2; o > 0; o >>= 1) {
        if (t < o) s[t] += s[t + o];
        __syncthreads();
    }
    if (t == 0) g_bsum[blockIdx.x] = s[0];
}

__global__ void k_scan2(int n) {
    __shared__ int s[256];
    int t = threadIdx.x;
    int v = (t < NBLK) ? g_bsum[t] : 0;
    s[t] = v;
    __syncthreads();
    for (int o = 1; o < 256; o <<= 1) {
        int x = (t >= o) ? s[t - o] : 0;
        __syncthreads();
        s[t] += x;
        __syncthreads();
    }
    if (t < NBLK) g_bpre[t] = s[t] - v;   // exclusive
    if (t == 255) g_off[n] = s[255];      // total = E
}

__global__ void k_scan3(int n) {
    __shared__ int s[CHUNK];
    int t = threadIdx.x;
    int idx = blockIdx.x * CHUNK + t;
    int v = (idx < n) ? g_cnt[idx] : 0;
    s[t] = v;
    __syncthreads();
    for (int o = 1; o < CHUNK; o <<= 1) {
        int x = (t >= o) ? s[t - o] : 0;
        __syncthreads();
        s[t] += x;
        __syncthreads();
    }
    if (idx < n) g_off[idx] = g_bpre[blockIdx.x] + s[t] - v;  // exclusive
}

// fill CSR with {src, dinv[src]*dinv[dst]} pairs (dinv ready by now)
__global__ void k_fill(const int* __restrict__ src, const int* __restrict__ dst, int e) {
    int i = blockIdx.x * blockDim.x + threadIdx.x;
    if (i < e) {
        int d = dst[i];
        int s = src[i];
        int p = atomicAdd(&g_cur[d], 1);
        float w = g_dinv[s] * g_dinv[d];
        g_ew[g_off[d] + p] = make_int2(s, __float_as_int(w));
    }
}

// ---------------- GEMM (tf32 tensor cores): g_half = in @ W ----------------
// first=1: fp32 input x. first=0: fp16 input g_hin (already relu'd).
__global__ void k_gemm_tc(const float* __restrict__ xin, const float* __restrict__ W,
                          int n, int first) {
    extern __shared__ float sm[];
    float* sW = sm;                 // 128 x WSTR
    float* sA = sm + 128 * WSTR;    // 64 x ASTR (doubles as C tile in epilogue)
    int t = threadIdx.x;

    for (int i = t; i < F * F; i += 256) {
        int k = i >> 7, f = i & 127;
        sW[k * WSTR + f] = wmma::__float_to_tf32(W[i]);
    }

    int warp = t >> 5;
    int wr = (warp & 1) * 32;
    int wc = (warp >> 1) * 32;

    int ntiles = (n + 63) >> 6;
    for (int tile = blockIdx.x; tile < ntiles; tile += gridDim.x) {
        int row0 = tile << 6;
        __syncthreads();            // protect sA reuse (and first-pass sW)
        if (first) {
            for (int i = t * 4; i < 64 * F; i += 256 * 4) {
                int r = i >> 7, k = i & 127;
                int rr = row0 + r;
                float4 v = make_float4(0.f, 0.f, 0.f, 0.f);
                if (rr < n) v = *(const float4*)&xin[rr * F + k];
                float* d = &sA[r * ASTR + k];
                d[0] = wmma::__float_to_tf32(v.x);
                d[1] = wmma::__float_to_tf32(v.y);
                d[2] = wmma::__float_to_tf32(v.z);
                d[3] = wmma::__float_to_tf32(v.w);
            }
        } else {
            for (int i = t * 8; i < 64 * F; i += 256 * 8) {
                int r = i >> 7, k = i & 127;
                int rr = row0 + r;
                uint4 u = make_uint4(0u, 0u, 0u, 0u);
                if (rr < n) u = *(const uint4*)&g_hin[rr * F + k];
                float* d = &sA[r * ASTR + k];
                float2 p0 = __half22float2(*reinterpret_cast<__half2*>(&u.x));
                float2 p1 = __half22float2(*reinterpret_cast<__half2*>(&u.y));
                float2 p2 = __half22float2(*reinterpret_cast<__half2*>(&u.z));
                float2 p3 = __half22float2(*reinterpret_cast<__half2*>(&u.w));
                d[0] = wmma::__float_to_tf32(p0.x); d[1] = wmma::__float_to_tf32(p0.y);
                d[2] = wmma::__float_to_tf32(p1.x); d[3] = wmma::__float_to_tf32(p1.y);
                d[4] = wmma::__float_to_tf32(p2.x); d[5] = wmma::__float_to_tf32(p2.y);
                d[6] = wmma::__float_to_tf32(p3.x); d[7] = wmma::__float_to_tf32(p3.y);
            }
        }
        __syncthreads();

        wmma::fragment<wmma::accumulator, 16, 16, 8, float> c[2][2];
        #pragma unroll
        for (int i = 0; i < 2; i++)
            #pragma unroll
            for (int j = 0; j < 2; j++)
                wmma::fill_fragment(c[i][j], 0.f);

        #pragma unroll
        for (int k0 = 0; k0 < F; k0 += 8) {
            wmma::fragment<wmma::matrix_a, 16, 16, 8, wmma::precision::tf32, wmma::row_major> a0, a1;
            wmma::fragment<wmma::matrix_b, 16, 16, 8, wmma::precision::tf32, wmma::row_major> b0, b1;
            wmma::load_matrix_sync(a0, &sA[wr * ASTR + k0], ASTR);
            wmma::load_matrix_sync(a1, &sA[(wr + 16) * ASTR + k0], ASTR);
            wmma::load_matrix_sync(b0, &sW[k0 * WSTR + wc], WSTR);
            wmma::load_matrix_sync(b1, &sW[k0 * WSTR + wc + 16], WSTR);
            wmma::mma_sync(c[0][0], a0, b0, c[0][0]);
            wmma::mma_sync(c[0][1], a0, b1, c[0][1]);
            wmma::mma_sync(c[1][0], a1, b0, c[1][0]);
            wmma::mma_sync(c[1][1], a1, b1, c[1][1]);
        }

        __syncthreads();            // all warps done reading sA
        #pragma unroll
        for (int i = 0; i < 2; i++)
            #pragma unroll
            for (int j = 0; j < 2; j++)
                wmma::store_matrix_sync(&sA[(wr + 16 * i) * ASTR + wc + 16 * j],
                                        c[i][j], ASTR, wmma::mem_row_major);
        __syncthreads();

        for (int i = t * 4; i < 64 * F; i += 256 * 4) {
            int r = i >> 7, k = i & 127;
            float4 v = *(const float4*)&sA[r * ASTR + k];
            __half2 h0 = __floats2half2_rn(v.x, v.y);
            __half2 h1 = __floats2half2_rn(v.z, v.w);
            uint2 u;
            u.x = *reinterpret_cast<unsigned*>(&h0);
            u.y = *reinterpret_cast<unsigned*>(&h1);
            *(uint2*)&g_half[(row0 + r) * F + k] = u;
        }
    }
}

// ---------------- Aggregation ----------------
// Half-warp (16 lanes) per node, lane owns 8 features (uint4 fp16 = 16B).
// g_hin[d] = relu( sum_in w*hl[s] + selfw*hl[d] + bias ), fp16 output.
__global__ void k_agg(const float* __restrict__ bias, int n) {
    int tid = blockIdx.x * blockDim.x + threadIdx.x;
    int hw = tid >> 4;
    int lane = tid & 15;
    int nhw = (gridDim.x * blockDim.x) >> 4;
    int fo = lane * 8;
    const __half* hl = g_half;
    const float4 bl = *(const float4*)&bias[fo];
    const float4 bh = *(const float4*)&bias[fo + 4];

    for (int nd = hw; nd < n; nd += nhw) {
        float dn = g_dinv[nd];
        float sw = dn * dn;
        float acc[8];
        {
            uint4 u = *(const uint4*)&hl[nd * F + fo];
            float2 p0 = __half22float2(*reinterpret_cast<__half2*>(&u.x));
            float2 p1 = __half22float2(*reinterpret_cast<__half2*>(&u.y));
            float2 p2 = __half22float2(*reinterpret_cast<__half2*>(&u.z));
            float2 p3 = __half22float2(*reinterpret_cast<__half2*>(&u.w));
            acc[0] = p0.x * sw; acc[1] = p0.y * sw;
            acc[2] = p1.x * sw; acc[3] = p1.y * sw;
            acc[4] = p2.x * sw; acc[5] = p2.y * sw;
            acc[6] = p3.x * sw; acc[7] = p3.y * sw;
        }
        int i = g_off[nd], iend = g_off[nd + 1];
        for (; i + 2 <= iend; i += 2) {
            int2 e0 = g_ew[i], e1 = g_ew[i + 1];
            float w0 = __int_as_float(e0.y), w1 = __int_as_float(e1.y);
            uint4 u0 = *(const uint4*)&hl[e0.x * F + fo];
            uint4 u1 = *(const uint4*)&hl[e1.x * F + fo];
            float2 a0 = __half22float2(*reinterpret_cast<__half2*>(&u0.x));
            float2 a1 = __half22float2(*reinterpret_cast<__half2*>(&u0.y));
            float2 a2 = __half22float2(*reinterpret_cast<__half2*>(&u0.z));
            float2 a3 = __half22float2(*reinterpret_cast<__half2*>(&u0.w));
            float2 c0 = __half22float2(*reinterpret_cast<__half2*>(&u1.x));
            float2 c1 = __half22float2(*reinterpret_cast<__half2*>(&u1.y));
            float2 c2 = __half22float2(*reinterpret_cast<__half2*>(&u1.z));
            float2 c3 = __half22float2(*reinterpret_cast<__half2*>(&u1.w));
            acc[0] = fmaf(a0.x, w0, fmaf(c0.x, w1, acc[0]));
            acc[1] = fmaf(a0.y, w0, fmaf(c0.y, w1, acc[1]));
            acc[2] = fmaf(a1.x, w0, fmaf(c1.x, w1, acc[2]));
            acc[3] = fmaf(a1.y, w0, fmaf(c1.y, w1, acc[3]));
            acc[4] = fmaf(a2.x, w0, fmaf(c2.x, w1, acc[4]));
            acc[5] = fmaf(a2.y, w0, fmaf(c2.y, w1, acc[5]));
            acc[6] = fmaf(a3.x, w0, fmaf(c3.x, w1, acc[6]));
            acc[7] = fmaf(a3.y, w0, fmaf(c3.y, w1, acc[7]));
        }
        if (i < iend) {
            int2 e0 = g_ew[i];
            float w0 = __int_as_float(e0.y);
            uint4 u0 = *(const uint4*)&hl[e0.x * F + fo];
            float2 a0 = __half22float2(*reinterpret_cast<__half2*>(&u0.x));
            float2 a1 = __half22float2(*reinterpret_cast<__half2*>(&u0.y));
            float2 a2 = __half22float2(*reinterpret_cast<__half2*>(&u0.z));
            float2 a3 = __half22float2(*reinterpret_cast<__half2*>(&u0.w));
            acc[0] = fmaf(a0.x, w0, acc[0]); acc[1] = fmaf(a0.y, w0, acc[1]);
            acc[2] = fmaf(a1.x, w0, acc[2]); acc[3] = fmaf(a1.y, w0, acc[3]);
            acc[4] = fmaf(a2.x, w0, acc[4]); acc[5] = fmaf(a2.y, w0, acc[5]);
            acc[6] = fmaf(a3.x, w0, acc[6]); acc[7] = fmaf(a3.y, w0, acc[7]);
        }
        // bias + relu + fp16 pack
        acc[0] = fmaxf(acc[0] + bl.x, 0.f); acc[1] = fmaxf(acc[1] + bl.y, 0.f);
        acc[2] = fmaxf(acc[2] + bl.z, 0.f); acc[3] = fmaxf(acc[3] + bl.w, 0.f);
        acc[4] = fmaxf(acc[4] + bh.x, 0.f); acc[5] = fmaxf(acc[5] + bh.y, 0.f);
        acc[6] = fmaxf(acc[6] + bh.z, 0.f); acc[7] = fmaxf(acc[7] + bh.w, 0.f);
        __half2 h0 = __floats2half2_rn(acc[0], acc[1]);
        __half2 h1 = __floats2half2_rn(acc[2], acc[3]);
        __half2 h2 = __floats2half2_rn(acc[4], acc[5]);
        __half2 h3 = __floats2half2_rn(acc[6], acc[7]);
        uint4 o;
        o.x = *reinterpret_cast<unsigned*>(&h0);
        o.y = *reinterpret_cast<unsigned*>(&h1);
        o.z = *reinterpret_cast<unsigned*>(&h2);
        o.w = *reinterpret_cast<unsigned*>(&h3);
        *(uint4*)&g_hin[nd * F + fo] = o;
    }
}

// ---------------- Pooling: segment_max over relu'd fp16 h ----------------
__global__ void k_pool(const int* __restrict__ batch, int n) {
    int f = threadIdx.x;
    int n0 = blockIdx.x * CHUNK;
    if (n0 >= n) return;
    int n1 = min(n0 + CHUNK, n);
    int cur = batch[n0];
    float m = 0.f;
    for (int nd = n0; nd < n1; nd++) {
        int gg = batch[nd];
        if (gg != cur) {
            atomicMax((int*)&g_pooled[cur * F + f], __float_as_int(m));
            cur = gg;
            m = 0.f;
        }
        m = fmaxf(m, __half2float(g_hin[nd * F + f]));
    }
    atomicMax((int*)&g_pooled[cur * F + f], __float_as_int(m));
}

// ---------------- Head ----------------
__global__ void k_head(const float* __restrict__ Wp1, const float* __restrict__ bp1,
                       const float* __restrict__ Wp2, const float* __restrict__ bp2,
                       float* __restrict__ out) {
    __shared__ float sp[F];
    __shared__ float t1[F];
    int t = threadIdx.x, g = blockIdx.x;
    sp[t] = g_pooled[g * F + t];
    __syncthreads();
    float a = bp1[t];
    #pragma unroll 4
    for (int k = 0; k < F; k++) a = fmaf(sp[k], Wp1[k * F + t], a);
    t1[t] = a;
    __syncthreads();
    if (t == 0) {
        float l0 = bp2[0], l1 = bp2[1];
        for (int k = 0; k < F; k++) {
            l0 = fmaf(t1[k], Wp2[2 * k], l0);
            l1 = fmaf(t1[k], Wp2[2 * k + 1], l1);
        }
        float m = fmaxf(l0, l1);
        float lse = m + logf(expf(l0 - m) + expf(l1 - m));
        out[2 * g] = l0 - lse;
        out[2 * g + 1] = l1 - lse;
    }
}

// ---------------- launch ----------------
extern "C" void kernel_launch(void* const* d_in, const int* in_sizes, int n_in,
                              void* d_out, int out_size) {
    const float* x   = (const float*)d_in[0];
    const int*   ei  = (const int*)d_in[1];
    const int*   bat = (const int*)d_in[2];
    const float* W1  = (const float*)d_in[3];  const float* b1  = (const float*)d_in[4];
    const float* W2  = (const float*)d_in[5];  const float* b2  = (const float*)d_in[6];
    const float* W3  = (const float*)d_in[7];  const float* b3  = (const float*)d_in[8];
    const float* Wp1 = (const float*)d_in[9];  const float* bp1 = (const float*)d_in[10];
    const float* Wp2 = (const float*)d_in[11]; const float* bp2 = (const float*)d_in[12];
    float* out = (float*)d_out;

    int n = in_sizes[0] / F;        // 100000
    int e = in_sizes[1] / 2;        // 1600000
    const int* src = ei;
    const int* dst = ei + e;

    size_t smem = (size_t)(128 * WSTR + 64 * ASTR) * sizeof(float);   // 101376 B
    cudaFuncSetAttribute(k_gemm_tc, cudaFuncAttributeMaxDynamicSharedMemorySize, (int)smem);

    k_zero<<<(NN + 255) / 256, 256>>>();
    k_count<<<(e + 255) / 256, 256>>>(dst, e);
    k_dinv<<<(n + 255) / 256, 256>>>(n);
    k_scan1<<<NBLK, CHUNK>>>(n);
    k_scan2<<<1, 256>>>(n);
    k_scan3<<<NBLK, CHUNK>>>(n);
    k_fill<<<(e + 255) / 256, 256>>>(src, dst, e);

    k_gemm_tc<<<296, 256, smem>>>(x, W1, n, 1);
    k_agg<<<1184, 256>>>(b1, n);
    k_gemm_tc<<<296, 256, smem>>>(x, W2, n, 0);
    k_agg<<<1184, 256>>>(b2, n);
    k_gemm_tc<<<296, 256, smem>>>(x, W3, n, 0);
    k_agg<<<1184, 256>>>(b3, n);

    k_pool<<<NBLK, F>>>(bat, n);
    k_head<<<G, F>>>(Wp1, bp1, Wp2, bp2, out);
}

// round 6
// speedup vs baseline: 1.9410x; 1.3855x over previous
#include <cuda_runtime.h>
#include <cuda_fp16.h>
#include <mma.h>
#include <math.h>

using namespace nvcuda;

#define NN 100000
#define NPAD (NN + 64)
#define EE 1600000
#define F  128
#define G  64
#define CHUNK 512
#define NBLK ((NN + CHUNK - 1) / CHUNK)   // 196
#define WSTRH 136
#define ASTRH 136
#define CSTR  132

// ---------------- device scratch (allocation-free) ----------------
__device__ __half g_half[NPAD * F];  // hl = h @ W, fp16          (25.6 MB)
__device__ __half g_hin[NPAD * F];   // relu(agg) output, fp16    (25.6 MB)
__device__ float  g_dinv[NN];
__device__ int    g_cnt[NN];
__device__ int    g_cur[NN];
__device__ int    g_off[NN + 1];
__device__ int2   g_ew[EE];          // {src, norm weight bits}   (12.8 MB)
__device__ int    g_bsum[NBLK];
__device__ int    g_bpre[NBLK];
__device__ float  g_pooled[G * F];

// ---------------- setup: degree, dinv, CSR ----------------
__global__ void k_zero() {
    int i = blockIdx.x * blockDim.x + threadIdx.x;
    if (i < NN) { g_cnt[i] = 0; g_cur[i] = 0; }
    if (i < G * F) g_pooled[i] = 0.f;
}

__global__ void k_count(const int* __restrict__ dst, int e) {
    int i = blockIdx.x * blockDim.x + threadIdx.x;
    if (i < e) atomicAdd(&g_cnt[dst[i]], 1);
}

// block-sum of counts + dinv (fused)
__global__ void k_scan1(int n) {
    __shared__ int s[CHUNK];
    int t = threadIdx.x;
    int idx = blockIdx.x * CHUNK + t;
    int c = (idx < n) ? g_cnt[idx] : 0;
    if (idx < n) g_dinv[idx] = rsqrtf((float)(c + 1));   // +1 self loop
    s[t] = c;
    __syncthreads();
    for (int o = CHUNK / 2; o > 0; o >>= 1) {
        if (t < o) s[t] += s[t + o];
        __syncthreads();
    }
    if (t == 0) g_bsum[blockIdx.x] = s[0];
}

__global__ void k_scan2(int n) {
    __shared__ int s[256];
    int t = threadIdx.x;
    int v = (t < NBLK) ? g_bsum[t] : 0;
    s[t] = v;
    __syncthreads();
    for (int o = 1; o < 256; o <<= 1) {
        int x = (t >= o) ? s[t - o] : 0;
        __syncthreads();
        s[t] += x;
        __syncthreads();
    }
    if (t < NBLK) g_bpre[t] = s[t] - v;   // exclusive
    if (t == 255) g_off[n] = s[255];      // total = E
}

__global__ void k_scan3(int n) {
    __shared__ int s[CHUNK];
    int t = threadIdx.x;
    int idx = blockIdx.x * CHUNK + t;
    int v = (idx < n) ? g_cnt[idx] : 0;
    s[t] = v;
    __syncthreads();
    for (int o = 1; o < CHUNK; o <<= 1) {
        int x = (t >= o) ? s[t - o] : 0;
        __syncthreads();
        s[t] += x;
        __syncthreads();
    }
    if (idx < n) g_off[idx] = g_bpre[blockIdx.x] + s[t] - v;  // exclusive
}

// fill CSR with {src, dinv[src]*dinv[dst]} pairs (dinv ready by now)
__global__ void k_fill(const int* __restrict__ src, const int* __restrict__ dst, int e) {
    int i = blockIdx.x * blockDim.x + threadIdx.x;
    if (i < e) {
        int d = dst[i];
        int s = src[i];
        int p = atomicAdd(&g_cur[d], 1);
        float w = g_dinv[s] * g_dinv[d];
        g_ew[g_off[d] + p] = make_int2(s, __float_as_int(w));
    }
}

// ---------------- GEMM (fp16 tensor cores, fp32 acc): g_half = in @ W ----------------
// first=1: fp32 input x (converted at staging). first=0: fp16 input g_hin.
// smem: sW half[128*WSTRH] (34.8KB) + region aliased as sA half / sC float (33.8KB).
__global__ void k_gemm_h(const float* __restrict__ xin, const float* __restrict__ W,
                         int n, int first) {
    extern __shared__ char smraw[];
    __half* sW = (__half*)smraw;                       // 128 x WSTRH halves
    __half* sA = (__half*)(smraw + 128 * WSTRH * 2);   // 64 x ASTRH halves
    float*  sC = (float*)(smraw + 128 * WSTRH * 2);    // 64 x CSTR floats (alias)
    int t = threadIdx.x;

    // stage W [k][f] as fp16
    for (int i = t * 2; i < F * F; i += 256 * 2) {
        int k = i >> 7, f = i & 127;
        __half2 h = __floats2half2_rn(W[i], W[i + 1]);
        *(__half2*)&sW[k * WSTRH + f] = h;
    }

    int warp = t >> 5;
    int wr = (warp & 1) * 32;
    int wc = (warp >> 1) * 32;

    int ntiles = (n + 63) >> 6;
    for (int tile = blockIdx.x; tile < ntiles; tile += gridDim.x) {
        int row0 = tile << 6;
        __syncthreads();            // protect sA/sC reuse (and first-pass sW)
        if (first) {
            for (int i = t * 8; i < 64 * F; i += 256 * 8) {
                int r = i >> 7, k = i & 127;
                int rr = row0 + r;
                float4 v0 = make_float4(0.f, 0.f, 0.f, 0.f), v1 = v0;
                if (rr < n) {
                    v0 = *(const float4*)&xin[rr * F + k];
                    v1 = *(const float4*)&xin[rr * F + k + 4];
                }
                __half2 h0 = __floats2half2_rn(v0.x, v0.y);
                __half2 h1 = __floats2half2_rn(v0.z, v0.w);
                __half2 h2 = __floats2half2_rn(v1.x, v1.y);
                __half2 h3 = __floats2half2_rn(v1.z, v1.w);
                uint4 u;
                u.x = *reinterpret_cast<unsigned*>(&h0);
                u.y = *reinterpret_cast<unsigned*>(&h1);
                u.z = *reinterpret_cast<unsigned*>(&h2);
                u.w = *reinterpret_cast<unsigned*>(&h3);
                *(uint4*)&sA[r * ASTRH + k] = u;
            }
        } else {
            for (int i = t * 8; i < 64 * F; i += 256 * 8) {
                int r = i >> 7, k = i & 127;
                int rr = row0 + r;
                uint4 u = make_uint4(0u, 0u, 0u, 0u);
                if (rr < n) u = *(const uint4*)&g_hin[rr * F + k];
                *(uint4*)&sA[r * ASTRH + k] = u;
            }
        }
        __syncthreads();

        wmma::fragment<wmma::accumulator, 16, 16, 16, float> c[2][2];
        #pragma unroll
        for (int i = 0; i < 2; i++)
            #pragma unroll
            for (int j = 0; j < 2; j++)
                wmma::fill_fragment(c[i][j], 0.f);

        #pragma unroll
        for (int k0 = 0; k0 < F; k0 += 16) {
            wmma::fragment<wmma::matrix_a, 16, 16, 16, __half, wmma::row_major> a0, a1;
            wmma::fragment<wmma::matrix_b, 16, 16, 16, __half, wmma::row_major> b0, b1;
            wmma::load_matrix_sync(a0, &sA[wr * ASTRH + k0], ASTRH);
            wmma::load_matrix_sync(a1, &sA[(wr + 16) * ASTRH + k0], ASTRH);
            wmma::load_matrix_sync(b0, &sW[k0 * WSTRH + wc], WSTRH);
            wmma::load_matrix_sync(b1, &sW[k0 * WSTRH + wc + 16], WSTRH);
            wmma::mma_sync(c[0][0], a0, b0, c[0][0]);
            wmma::mma_sync(c[0][1], a0, b1, c[0][1]);
            wmma::mma_sync(c[1][0], a1, b0, c[1][0]);
            wmma::mma_sync(c[1][1], a1, b1, c[1][1]);
        }

        __syncthreads();            // all warps done reading sA
        #pragma unroll
        for (int i = 0; i < 2; i++)
            #pragma unroll
            for (int j = 0; j < 2; j++)
                wmma::store_matrix_sync(&sC[(wr + 16 * i) * CSTR + wc + 16 * j],
                                        c[i][j], CSTR, wmma::mem_row_major);
        __syncthreads();

        // pack C tile to fp16, write to g_half (padded, unguarded)
        for (int i = t * 4; i < 64 * F; i += 256 * 4) {
            int r = i >> 7, k = i & 127;
            float4 v = *(const float4*)&sC[r * CSTR + k];
            __half2 h0 = __floats2half2_rn(v.x, v.y);
            __half2 h1 = __floats2half2_rn(v.z, v.w);
            uint2 u;
            u.x = *reinterpret_cast<unsigned*>(&h0);
            u.y = *reinterpret_cast<unsigned*>(&h1);
            *(uint2*)&g_half[(row0 + r) * F + k] = u;
        }
    }
}

// ---------------- Aggregation ----------------
// Half-warp (16 lanes) per node, lane owns 8 features (uint4 fp16 = 16B).
// g_hin[d] = relu( sum_in w*hl[s] + selfw*hl[d] + bias ), fp16 output.
__global__ void k_agg(const float* __restrict__ bias, int n) {
    int tid = blockIdx.x * blockDim.x + threadIdx.x;
    int hw = tid >> 4;
    int lane = tid & 15;
    int nhw = (gridDim.x * blockDim.x) >> 4;
    int fo = lane * 8;
    const __half* hl = g_half;
    const float4 bl = *(const float4*)&bias[fo];
    const float4 bh = *(const float4*)&bias[fo + 4];

    for (int nd = hw; nd < n; nd += nhw) {
        float dn = g_dinv[nd];
        float sw = dn * dn;
        float acc[8];
        {
            uint4 u = *(const uint4*)&hl[nd * F + fo];
            float2 p0 = __half22float2(*reinterpret_cast<__half2*>(&u.x));
            float2 p1 = __half22float2(*reinterpret_cast<__half2*>(&u.y));
            float2 p2 = __half22float2(*reinterpret_cast<__half2*>(&u.z));
            float2 p3 = __half22float2(*reinterpret_cast<__half2*>(&u.w));
            acc[0] = p0.x * sw; acc[1] = p0.y * sw;
            acc[2] = p1.x * sw; acc[3] = p1.y * sw;
            acc[4] = p2.x * sw; acc[5] = p2.y * sw;
            acc[6] = p3.x * sw; acc[7] = p3.y * sw;
        }
        int i = g_off[nd], iend = g_off[nd + 1];
        for (; i + 4 <= iend; i += 4) {
            int2 e[4];
            uint4 u[4];
            #pragma unroll
            for (int j = 0; j < 4; j++) e[j] = g_ew[i + j];
            #pragma unroll
            for (int j = 0; j < 4; j++) u[j] = *(const uint4*)&hl[e[j].x * F + fo];
            #pragma unroll
            for (int j = 0; j < 4; j++) {
                float w = __int_as_float(e[j].y);
                float2 a0 = __half22float2(*reinterpret_cast<__half2*>(&u[j].x));
                float2 a1 = __half22float2(*reinterpret_cast<__half2*>(&u[j].y));
                float2 a2 = __half22float2(*reinterpret_cast<__half2*>(&u[j].z));
                float2 a3 = __half22float2(*reinterpret_cast<__half2*>(&u[j].w));
                acc[0] = fmaf(a0.x, w, acc[0]); acc[1] = fmaf(a0.y, w, acc[1]);
                acc[2] = fmaf(a1.x, w, acc[2]); acc[3] = fmaf(a1.y, w, acc[3]);
                acc[4] = fmaf(a2.x, w, acc[4]); acc[5] = fmaf(a2.y, w, acc[5]);
                acc[6] = fmaf(a3.x, w, acc[6]); acc[7] = fmaf(a3.y, w, acc[7]);
            }
        }
        for (; i < iend; i++) {
            int2 e0 = g_ew[i];
            float w0 = __int_as_float(e0.y);
            uint4 u0 = *(const uint4*)&hl[e0.x * F + fo];
            float2 a0 = __half22float2(*reinterpret_cast<__half2*>(&u0.x));
            float2 a1 = __half22float2(*reinterpret_cast<__half2*>(&u0.y));
            float2 a2 = __half22float2(*reinterpret_cast<__half2*>(&u0.z));
            float2 a3 = __half22float2(*reinterpret_cast<__half2*>(&u0.w));
            acc[0] = fmaf(a0.x, w0, acc[0]); acc[1] = fmaf(a0.y, w0, acc[1]);
            acc[2] = fmaf(a1.x, w0, acc[2]); acc[3] = fmaf(a1.y, w0, acc[3]);
            acc[4] = fmaf(a2.x, w0, acc[4]); acc[5] = fmaf(a2.y, w0, acc[5]);
            acc[6] = fmaf(a3.x, w0, acc[6]); acc[7] = fmaf(a3.y, w0, acc[7]);
        }
        acc[0] = fmaxf(acc[0] + bl.x, 0.f); acc[1] = fmaxf(acc[1] + bl.y, 0.f);
        acc[2] = fmaxf(acc[2] + bl.z, 0.f); acc[3] = fmaxf(acc[3] + bl.w, 0.f);
        acc[4] = fmaxf(acc[4] + bh.x, 0.f); acc[5] = fmaxf(acc[5] + bh.y, 0.f);
        acc[6] = fmaxf(acc[6] + bh.z, 0.f); acc[7] = fmaxf(acc[7] + bh.w, 0.f);
        __half2 h0 = __floats2half2_rn(acc[0], acc[1]);
        __half2 h1 = __floats2half2_rn(acc[2], acc[3]);
        __half2 h2 = __floats2half2_rn(acc[4], acc[5]);
        __half2 h3 = __floats2half2_rn(acc[6], acc[7]);
        uint4 o;
        o.x = *reinterpret_cast<unsigned*>(&h0);
        o.y = *reinterpret_cast<unsigned*>(&h1);
        o.z = *reinterpret_cast<unsigned*>(&h2);
        o.w = *reinterpret_cast<unsigned*>(&h3);
        *(uint4*)&g_hin[nd * F + fo] = o;
    }
}

// ---------------- Pooling: segment_max over relu'd fp16 h ----------------
__global__ void k_pool(const int* __restrict__ batch, int n) {
    int f = threadIdx.x;
    int n0 = blockIdx.x * CHUNK;
    if (n0 >= n) return;
    int n1 = min(n0 + CHUNK, n);
    int cur = batch[n0];
    float m = 0.f;
    for (int nd = n0; nd < n1; nd++) {
        int gg = batch[nd];
        if (gg != cur) {
            atomicMax((int*)&g_pooled[cur * F + f], __float_as_int(m));
            cur = gg;
            m = 0.f;
        }
        m = fmaxf(m, __half2float(g_hin[nd * F + f]));
    }
    atomicMax((int*)&g_pooled[cur * F + f], __float_as_int(m));
}

// ---------------- Head ----------------
__global__ void k_head(const float* __restrict__ Wp1, const float* __restrict__ bp1,
                       const float* __restrict__ Wp2, const float* __restrict__ bp2,
                       float* __restrict__ out) {
    __shared__ float sp[F];
    __shared__ float t1[F];
    int t = threadIdx.x, g = blockIdx.x;
    sp[t] = g_pooled[g * F + t];
    __syncthreads();
    float a = bp1[t];
    #pragma unroll 4
    for (int k = 0; k < F; k++) a = fmaf(sp[k], Wp1[k * F + t], a);
    t1[t] = a;
    __syncthreads();
    if (t == 0) {
        float l0 = bp2[0], l1 = bp2[1];
        for (int k = 0; k < F; k++) {
            l0 = fmaf(t1[k], Wp2[2 * k], l0);
            l1 = fmaf(t1[k], Wp2[2 * k + 1], l1);
        }
        float m = fmaxf(l0, l1);
        float lse = m + logf(expf(l0 - m) + expf(l1 - m));
        out[2 * g] = l0 - lse;
        out[2 * g + 1] = l1 - lse;
    }
}

// ---------------- launch ----------------
extern "C" void kernel_launch(void* const* d_in, const int* in_sizes, int n_in,
                              void* d_out, int out_size) {
    const float* x   = (const float*)d_in[0];
    const int*   ei  = (const int*)d_in[1];
    const int*   bat = (const int*)d_in[2];
    const float* W1  = (const float*)d_in[3];  const float* b1  = (const float*)d_in[4];
    const float* W2  = (const float*)d_in[5];  const float* b2  = (const float*)d_in[6];
    const float* W3  = (const float*)d_in[7];  const float* b3  = (const float*)d_in[8];
    const float* Wp1 = (const float*)d_in[9];  const float* bp1 = (const float*)d_in[10];
    const float* Wp2 = (const float*)d_in[11]; const float* bp2 = (const float*)d_in[12];
    float* out = (float*)d_out;

    int n = in_sizes[0] / F;        // 100000
    int e = in_sizes[1] / 2;        // 1600000
    const int* src = ei;
    const int* dst = ei + e;

    size_t smem = 128 * WSTRH * 2 + 64 * CSTR * 4;     // 34816 + 33792 = 68608 B
    cudaFuncSetAttribute(k_gemm_h, cudaFuncAttributeMaxDynamicSharedMemorySize, (int)smem);

    k_zero<<<(NN + 255) / 256, 256>>>();                   // idx 0
    k_count<<<(e + 255) / 256, 256>>>(dst, e);             // idx 1
    k_scan1<<<NBLK, CHUNK>>>(n);                           // idx 2 (+dinv)
    k_gemm_h<<<444, 256, smem>>>(x, W1, n, 1);             // idx 3  <-- profiler target
    k_scan2<<<1, 256>>>(n);                                // idx 4
    k_scan3<<<NBLK, CHUNK>>>(n);                           // idx 5
    k_fill<<<(e + 255) / 256, 256>>>(src, dst, e);         // idx 6

    k_agg<<<1184, 256>>>(b1, n);
    k_gemm_h<<<444, 256, smem>>>(x, W2, n, 0);
    k_agg<<<1184, 256>>>(b2, n);
    k_gemm_h<<<444, 256, smem>>>(x, W3, n, 0);
    k_agg<<<1184, 256>>>(b3, n);

    k_pool<<<NBLK, F>>>(bat, n);
    k_head<<<G, F>>>(Wp1, bp1, Wp2, bp2, out);
}

// round 7
// speedup vs baseline: 2.0307x; 1.0462x over previous
#include <cuda_runtime.h>
#include <cuda_fp16.h>
#include <mma.h>
#include <math.h>

using namespace nvcuda;

#define NN 100000
#define NPAD (NN + 64)
#define EE 1600000
#define EWSZ (EE + 4 * NN + 8)
#define F  128
#define G  64
#define CHUNK 512
#define NBLK ((NN + CHUNK - 1) / CHUNK)   // 196
#define WSTRH 136
#define ASTRH 136
#define CSTR  132

// ---------------- device scratch (allocation-free) ----------------
__device__ __half g_half[NPAD * F];  // hl = h @ W, fp16          (25.6 MB)
__device__ __half g_hin[NPAD * F];   // relu(agg) output, fp16    (25.6 MB)
__device__ float  g_dinv[NN];
__device__ int    g_cnt[NN];
__device__ int    g_cur[NN];
__device__ int    g_off[NN + 1];
__device__ int2   g_ew[EWSZ];        // {src, norm weight bits}, padded + guard
__device__ int    g_bsum[NBLK];
__device__ int    g_bpre[NBLK];
__device__ float  g_pooled[G * F];

// ---------------- setup: degree, dinv, padded CSR ----------------
__global__ void k_zero() {
    int i = blockIdx.x * blockDim.x + threadIdx.x;
    if (i < NN) { g_cnt[i] = 0; g_cur[i] = 0; }
    if (i < G * F) g_pooled[i] = 0.f;
}

__global__ void k_count(const int* __restrict__ dst, int e) {
    int i = blockIdx.x * blockDim.x + threadIdx.x;
    if (i < e) atomicAdd(&g_cnt[dst[i]], 1);
}

// block-sum of PADDED counts + dinv (fused)
__global__ void k_scan1(int n) {
    __shared__ int s[CHUNK];
    int t = threadIdx.x;
    int idx = blockIdx.x * CHUNK + t;
    int c = (idx < n) ? g_cnt[idx] : 0;
    if (idx < n) g_dinv[idx] = rsqrtf((float)(c + 1));   // +1 self loop
    s[t] = (c + 3) & ~3;                                 // padded to mult of 4
    __syncthreads();
    for (int o = CHUNK / 2; o > 0; o >>= 1) {
        if (t < o) s[t] += s[t + o];
        __syncthreads();
    }
    if (t == 0) g_bsum[blockIdx.x] = s[0];
}

__global__ void k_scan2(int n) {
    __shared__ int s[256];
    int t = threadIdx.x;
    int v = (t < NBLK) ? g_bsum[t] : 0;
    s[t] = v;
    __syncthreads();
    for (int o = 1; o < 256; o <<= 1) {
        int x = (t >= o) ? s[t - o] : 0;
        __syncthreads();
        s[t] += x;
        __syncthreads();
    }
    if (t < NBLK) g_bpre[t] = s[t] - v;   // exclusive
    if (t == 255) g_off[n] = s[255];      // total padded
}

__global__ void k_scan3(int n) {
    __shared__ int s[CHUNK];
    int t = threadIdx.x;
    int idx = blockIdx.x * CHUNK + t;
    int v = (idx < n) ? ((g_cnt[idx] + 3) & ~3) : 0;
    s[t] = v;
    __syncthreads();
    for (int o = 1; o < CHUNK; o <<= 1) {
        int x = (t >= o) ? s[t - o] : 0;
        __syncthreads();
        s[t] += x;
        __syncthreads();
    }
    if (idx < n) g_off[idx] = g_bpre[blockIdx.x] + s[t] - v;  // exclusive
}

// fill CSR with {src, dinv[src]*dinv[dst]} pairs
__global__ void k_fill(const int* __restrict__ src, const int* __restrict__ dst, int e) {
    int i = blockIdx.x * blockDim.x + threadIdx.x;
    if (i < e) {
        int d = dst[i];
        int s = src[i];
        int p = atomicAdd(&g_cur[d], 1);
        float w = g_dinv[s] * g_dinv[d];
        g_ew[g_off[d] + p] = make_int2(s, __float_as_int(w));
    }
}

// fill per-node padding slots (zero-weight edges) + guard region
__global__ void k_pad(int n) {
    int i = blockIdx.x * blockDim.x + threadIdx.x;
    if (i < n) {
        int s0 = g_off[i] + g_cnt[i];
        int s1 = g_off[i + 1];
        for (int s = s0; s < s1; s++) g_ew[s] = make_int2(0, 0);
    }
    if (i < 8) g_ew[g_off[n] + i] = make_int2(0, 0);   // prefetch guard
}

// ---------------- GEMM (fp16 tensor cores, fp32 acc): g_half = in @ W ----------------
__global__ void k_gemm_h(const float* __restrict__ xin, const float* __restrict__ W,
                         int n, int first) {
    extern __shared__ char smraw[];
    __half* sW = (__half*)smraw;                       // 128 x WSTRH halves
    __half* sA = (__half*)(smraw + 128 * WSTRH * 2);   // 64 x ASTRH halves
    float*  sC = (float*)(smraw + 128 * WSTRH * 2);    // 64 x CSTR floats (alias)
    int t = threadIdx.x;

    for (int i = t * 2; i < F * F; i += 256 * 2) {
        int k = i >> 7, f = i & 127;
        __half2 h = __floats2half2_rn(W[i], W[i + 1]);
        *(__half2*)&sW[k * WSTRH + f] = h;
    }

    int warp = t >> 5;
    int wr = (warp & 1) * 32;
    int wc = (warp >> 1) * 32;

    int ntiles = (n + 63) >> 6;
    for (int tile = blockIdx.x; tile < ntiles; tile += gridDim.x) {
        int row0 = tile << 6;
        __syncthreads();
        if (first) {
            for (int i = t * 8; i < 64 * F; i += 256 * 8) {
                int r = i >> 7, k = i & 127;
                int rr = row0 + r;
                float4 v0 = make_float4(0.f, 0.f, 0.f, 0.f), v1 = v0;
                if (rr < n) {
                    v0 = *(const float4*)&xin[rr * F + k];
                    v1 = *(const float4*)&xin[rr * F + k + 4];
                }
                __half2 h0 = __floats2half2_rn(v0.x, v0.y);
                __half2 h1 = __floats2half2_rn(v0.z, v0.w);
                __half2 h2 = __floats2half2_rn(v1.x, v1.y);
                __half2 h3 = __floats2half2_rn(v1.z, v1.w);
                uint4 u;
                u.x = *reinterpret_cast<unsigned*>(&h0);
                u.y = *reinterpret_cast<unsigned*>(&h1);
                u.z = *reinterpret_cast<unsigned*>(&h2);
                u.w = *reinterpret_cast<unsigned*>(&h3);
                *(uint4*)&sA[r * ASTRH + k] = u;
            }
        } else {
            for (int i = t * 8; i < 64 * F; i += 256 * 8) {
                int r = i >> 7, k = i & 127;
                int rr = row0 + r;
                uint4 u = make_uint4(0u, 0u, 0u, 0u);
                if (rr < n) u = *(const uint4*)&g_hin[rr * F + k];
                *(uint4*)&sA[r * ASTRH + k] = u;
            }
        }
        __syncthreads();

        wmma::fragment<wmma::accumulator, 16, 16, 16, float> c[2][2];
        #pragma unroll
        for (int i = 0; i < 2; i++)
            #pragma unroll
            for (int j = 0; j < 2; j++)
                wmma::fill_fragment(c[i][j], 0.f);

        #pragma unroll
        for (int k0 = 0; k0 < F; k0 += 16) {
            wmma::fragment<wmma::matrix_a, 16, 16, 16, __half, wmma::row_major> a0, a1;
            wmma::fragment<wmma::matrix_b, 16, 16, 16, __half, wmma::row_major> b0, b1;
            wmma::load_matrix_sync(a0, &sA[wr * ASTRH + k0], ASTRH);
            wmma::load_matrix_sync(a1, &sA[(wr + 16) * ASTRH + k0], ASTRH);
            wmma::load_matrix_sync(b0, &sW[k0 * WSTRH + wc], WSTRH);
            wmma::load_matrix_sync(b1, &sW[k0 * WSTRH + wc + 16], WSTRH);
            wmma::mma_sync(c[0][0], a0, b0, c[0][0]);
            wmma::mma_sync(c[0][1], a0, b1, c[0][1]);
            wmma::mma_sync(c[1][0], a1, b0, c[1][0]);
            wmma::mma_sync(c[1][1], a1, b1, c[1][1]);
        }

        __syncthreads();
        #pragma unroll
        for (int i = 0; i < 2; i++)
            #pragma unroll
            for (int j = 0; j < 2; j++)
                wmma::store_matrix_sync(&sC[(wr + 16 * i) * CSTR + wc + 16 * j],
                                        c[i][j], CSTR, wmma::mem_row_major);
        __syncthreads();

        for (int i = t * 4; i < 64 * F; i += 256 * 4) {
            int r = i >> 7, k = i & 127;
            float4 v = *(const float4*)&sC[r * CSTR + k];
            __half2 h0 = __floats2half2_rn(v.x, v.y);
            __half2 h1 = __floats2half2_rn(v.z, v.w);
            uint2 u;
            u.x = *reinterpret_cast<unsigned*>(&h0);
            u.y = *reinterpret_cast<unsigned*>(&h1);
            *(uint2*)&g_half[(row0 + r) * F + k] = u;
        }
    }
}

// ---------------- Aggregation (software-pipelined, padded batches of 4) ----
// Half-warp (16 lanes) per node, lane owns 8 features (uint4 fp16 = 16B).
__global__ void k_agg(const float* __restrict__ bias, int n) {
    int tid = blockIdx.x * blockDim.x + threadIdx.x;
    int hw = tid >> 4;
    int lane = tid & 15;
    int nhw = (gridDim.x * blockDim.x) >> 4;
    int fo = lane * 8;
    const __half* hl = g_half;
    const float4 bl = *(const float4*)&bias[fo];
    const float4 bh = *(const float4*)&bias[fo + 4];

    for (int nd = hw; nd < n; nd += nhw) {
        float dn = g_dinv[nd];
        float sw = dn * dn;
        float acc[8];
        {
            uint4 u = *(const uint4*)&hl[nd * F + fo];
            float2 p0 = __half22float2(*reinterpret_cast<__half2*>(&u.x));
            float2 p1 = __half22float2(*reinterpret_cast<__half2*>(&u.y));
            float2 p2 = __half22float2(*reinterpret_cast<__half2*>(&u.z));
            float2 p3 = __half22float2(*reinterpret_cast<__half2*>(&u.w));
            acc[0] = p0.x * sw; acc[1] = p0.y * sw;
            acc[2] = p1.x * sw; acc[3] = p1.y * sw;
            acc[4] = p2.x * sw; acc[5] = p2.y * sw;
            acc[6] = p3.x * sw; acc[7] = p3.y * sw;
        }
        int i = g_off[nd], iend = g_off[nd + 1];   // padded: multiple of 4
        if (i < iend) {
            int2 e0 = g_ew[i], e1 = g_ew[i + 1], e2 = g_ew[i + 2], e3 = g_ew[i + 3];
            while (true) {
                // gathers for current batch
                uint4 u0 = *(const uint4*)&hl[e0.x * F + fo];
                uint4 u1 = *(const uint4*)&hl[e1.x * F + fo];
                uint4 u2 = *(const uint4*)&hl[e2.x * F + fo];
                uint4 u3 = *(const uint4*)&hl[e3.x * F + fo];
                i += 4;
                // prefetch next batch metadata (guard region makes this safe)
                int2 f0 = g_ew[i], f1 = g_ew[i + 1], f2 = g_ew[i + 2], f3 = g_ew[i + 3];
                float w0 = __int_as_float(e0.y), w1 = __int_as_float(e1.y);
                float w2 = __int_as_float(e2.y), w3 = __int_as_float(e3.y);
                float2 a0 = __half22float2(*reinterpret_cast<__half2*>(&u0.x));
                float2 a1 = __half22float2(*reinterpret_cast<__half2*>(&u0.y));
                float2 a2 = __half22float2(*reinterpret_cast<__half2*>(&u0.z));
                float2 a3 = __half22float2(*reinterpret_cast<__half2*>(&u0.w));
                acc[0] = fmaf(a0.x, w0, acc[0]); acc[1] = fmaf(a0.y, w0, acc[1]);
                acc[2] = fmaf(a1.x, w0, acc[2]); acc[3] = fmaf(a1.y, w0, acc[3]);
                acc[4] = fmaf(a2.x, w0, acc[4]); acc[5] = fmaf(a2.y, w0, acc[5]);
                acc[6] = fmaf(a3.x, w0, acc[6]); acc[7] = fmaf(a3.y, w0, acc[7]);
                a0 = __half22float2(*reinterpret_cast<__half2*>(&u1.x));
                a1 = __half22float2(*reinterpret_cast<__half2*>(&u1.y));
                a2 = __half22float2(*reinterpret_cast<__half2*>(&u1.z));
                a3 = __half22float2(*reinterpret_cast<__half2*>(&u1.w));
                acc[0] = fmaf(a0.x, w1, acc[0]); acc[1] = fmaf(a0.y, w1, acc[1]);
                acc[2] = fmaf(a1.x, w1, acc[2]); acc[3] = fmaf(a1.y, w1, acc[3]);
                acc[4] = fmaf(a2.x, w1, acc[4]); acc[5] = fmaf(a2.y, w1, acc[5]);
                acc[6] = fmaf(a3.x, w1, acc[6]); acc[7] = fmaf(a3.y, w1, acc[7]);
                a0 = __half22float2(*reinterpret_cast<__half2*>(&u2.x));
                a1 = __half22float2(*reinterpret_cast<__half2*>(&u2.y));
                a2 = __half22float2(*reinterpret_cast<__half2*>(&u2.z));
                a3 = __half22float2(*reinterpret_cast<__half2*>(&u2.w));
                acc[0] = fmaf(a0.x, w2, acc[0]); acc[1] = fmaf(a0.y, w2, acc[1]);
                acc[2] = fmaf(a1.x, w2, acc[2]); acc[3] = fmaf(a1.y, w2, acc[3]);
                acc[4] = fmaf(a2.x, w2, acc[4]); acc[5] = fmaf(a2.y, w2, acc[5]);
                acc[6] = fmaf(a3.x, w2, acc[6]); acc[7] = fmaf(a3.y, w2, acc[7]);
                a0 = __half22float2(*reinterpret_cast<__half2*>(&u3.x));
                a1 = __half22float2(*reinterpret_cast<__half2*>(&u3.y));
                a2 = __half22float2(*reinterpret_cast<__half2*>(&u3.z));
                a3 = __half22float2(*reinterpret_cast<__half2*>(&u3.w));
                acc[0] = fmaf(a0.x, w3, acc[0]); acc[1] = fmaf(a0.y, w3, acc[1]);
                acc[2] = fmaf(a1.x, w3, acc[2]); acc[3] = fmaf(a1.y, w3, acc[3]);
                acc[4] = fmaf(a2.x, w3, acc[4]); acc[5] = fmaf(a2.y, w3, acc[5]);
                acc[6] = fmaf(a3.x, w3, acc[6]); acc[7] = fmaf(a3.y, w3, acc[7]);
                if (i >= iend) break;
                e0 = f0; e1 = f1; e2 = f2; e3 = f3;
            }
        }
        acc[0] = fmaxf(acc[0] + bl.x, 0.f); acc[1] = fmaxf(acc[1] + bl.y, 0.f);
        acc[2] = fmaxf(acc[2] + bl.z, 0.f); acc[3] = fmaxf(acc[3] + bl.w, 0.f);
        acc[4] = fmaxf(acc[4] + bh.x, 0.f); acc[5] = fmaxf(acc[5] + bh.y, 0.f);
        acc[6] = fmaxf(acc[6] + bh.z, 0.f); acc[7] = fmaxf(acc[7] + bh.w, 0.f);
        __half2 h0 = __floats2half2_rn(acc[0], acc[1]);
        __half2 h1 = __floats2half2_rn(acc[2], acc[3]);
        __half2 h2 = __floats2half2_rn(acc[4], acc[5]);
        __half2 h3 = __floats2half2_rn(acc[6], acc[7]);
        uint4 o;
        o.x = *reinterpret_cast<unsigned*>(&h0);
        o.y = *reinterpret_cast<unsigned*>(&h1);
        o.z = *reinterpret_cast<unsigned*>(&h2);
        o.w = *reinterpret_cast<unsigned*>(&h3);
        *(uint4*)&g_hin[nd * F + fo] = o;
    }
}

// ---------------- Pooling: segment_max over relu'd fp16 h ----------------
__global__ void k_pool(const int* __restrict__ batch, int n) {
    int f = threadIdx.x;
    int n0 = blockIdx.x * CHUNK;
    if (n0 >= n) return;
    int n1 = min(n0 + CHUNK, n);
    int cur = batch[n0];
    float m = 0.f;
    for (int nd = n0; nd < n1; nd++) {
        int gg = batch[nd];
        if (gg != cur) {
            atomicMax((int*)&g_pooled[cur * F + f], __float_as_int(m));
            cur = gg;
            m = 0.f;
        }
        m = fmaxf(m, __half2float(g_hin[nd * F + f]));
    }
    atomicMax((int*)&g_pooled[cur * F + f], __float_as_int(m));
}

// ---------------- Head ----------------
__global__ void k_head(const float* __restrict__ Wp1, const float* __restrict__ bp1,
                       const float* __restrict__ Wp2, const float* __restrict__ bp2,
                       float* __restrict__ out) {
    __shared__ float sp[F];
    __shared__ float t1[F];
    int t = threadIdx.x, g = blockIdx.x;
    sp[t] = g_pooled[g * F + t];
    __syncthreads();
    float a = bp1[t];
    #pragma unroll 4
    for (int k = 0; k < F; k++) a = fmaf(sp[k], Wp1[k * F + t], a);
    t1[t] = a;
    __syncthreads();
    if (t == 0) {
        float l0 = bp2[0], l1 = bp2[1];
        for (int k = 0; k < F; k++) {
            l0 = fmaf(t1[k], Wp2[2 * k], l0);
            l1 = fmaf(t1[k], Wp2[2 * k + 1], l1);
        }
        float m = fmaxf(l0, l1);
        float lse = m + logf(expf(l0 - m) + expf(l1 - m));
        out[2 * g] = l0 - lse;
        out[2 * g + 1] = l1 - lse;
    }
}

// ---------------- launch ----------------
extern "C" void kernel_launch(void* const* d_in, const int* in_sizes, int n_in,
                              void* d_out, int out_size) {
    const float* x   = (const float*)d_in[0];
    const int*   ei  = (const int*)d_in[1];
    const int*   bat = (const int*)d_in[2];
    const float* W1  = (const float*)d_in[3];  const float* b1  = (const float*)d_in[4];
    const float* W2  = (const float*)d_in[5];  const float* b2  = (const float*)d_in[6];
    const float* W3  = (const float*)d_in[7];  const float* b3  = (const float*)d_in[8];
    const float* Wp1 = (const float*)d_in[9];  const float* bp1 = (const float*)d_in[10];
    const float* Wp2 = (const float*)d_in[11]; const float* bp2 = (const float*)d_in[12];
    float* out = (float*)d_out;

    int n = in_sizes[0] / F;        // 100000
    int e = in_sizes[1] / 2;        // 1600000
    const int* src = ei;
    const int* dst = ei + e;

    size_t smem = 128 * WSTRH * 2 + 64 * CSTR * 4;     // 68608 B
    cudaFuncSetAttribute(k_gemm_h, cudaFuncAttributeMaxDynamicSharedMemorySize, (int)smem);

    k_zero<<<(NN + 255) / 256, 256>>>();                   // idx 0
    k_count<<<(e + 255) / 256, 256>>>(dst, e);             // idx 1
    k_scan1<<<NBLK, CHUNK>>>(n);                           // idx 2 (+dinv)
    k_gemm_h<<<444, 256, smem>>>(x, W1, n, 1);             // idx 3  <-- profiler target
    k_scan2<<<1, 256>>>(n);                                // idx 4
    k_scan3<<<NBLK, CHUNK>>>(n);                           // idx 5
    k_fill<<<(e + 255) / 256, 256>>>(src, dst, e);         // idx 6
    k_pad<<<(NN + 255) / 256, 256>>>(n);                   // idx 7

    k_agg<<<1184, 256>>>(b1, n);
    k_gemm_h<<<444, 256, smem>>>(x, W2, n, 0);
    k_agg<<<1184, 256>>>(b2, n);
    k_gemm_h<<<444, 256, smem>>>(x, W3, n, 0);
    k_agg<<<1184, 256>>>(b3, n);

    k_pool<<<NBLK, F>>>(bat, n);
    k_head<<<G, F>>>(Wp1, bp1, Wp2, bp2, out);
}